// round 17
// baseline (speedup 1.0000x reference)
#include <cuda_runtime.h>
#include <cstdint>

#define DDIM   4096
#define M_ROWS 8192
#define N_ROWS 4096
#define KINT   (DDIM / 4)          // 1024 ints per row

__device__ __align__(256) int8_t g_qx[(size_t)M_ROWS * DDIM];
__device__ __align__(256) int8_t g_qw[(size_t)N_ROWS * DDIM];
__device__ float g_sa[M_ROWS];
__device__ float g_sw[N_ROWS];

__device__ __forceinline__ uint32_t smem_u32(const void* p) {
    uint32_t a;
    asm("{ .reg .u64 t; cvta.to.shared.u64 t, %1; cvt.u32.u64 %0, t; }" : "=r"(a) : "l"(p));
    return a;
}
__device__ __forceinline__ void cp4(uint32_t dst, const void* src) {
    asm volatile("cp.async.ca.shared.global [%0], [%1], 4;" :: "r"(dst), "l"(src) : "memory");
}
#define CP_COMMIT()  asm volatile("cp.async.commit_group;" ::: "memory")
#define CP_WAIT(n)   asm volatile("cp.async.wait_group %0;" :: "n"(n) : "memory")

__device__ __forceinline__ void imma16832(int* c, const uint32_t* a, const uint32_t* b) {
    asm volatile(
        "mma.sync.aligned.m16n8k32.row.col.s32.s8.s8.s32 "
        "{%0,%1,%2,%3}, {%4,%5,%6,%7}, {%8,%9}, {%0,%1,%2,%3};\n"
        : "+r"(c[0]), "+r"(c[1]), "+r"(c[2]), "+r"(c[3])
        : "r"(a[0]), "r"(a[1]), "r"(a[2]), "r"(a[3]), "r"(b[0]), "r"(b[1]));
}

// ---------------- fused row-wise absmax int8 quantization ----------------
__global__ __launch_bounds__(256) void quant_fused_kernel(
    const float* __restrict__ x, const float* __restrict__ w,
    const float* __restrict__ scales)
{
    const int b    = blockIdx.x;
    const bool isx = (b < M_ROWS);
    const int row  = isx ? b : (b - M_ROWS);
    const int tid  = threadIdx.x;
    const float4* src4 = reinterpret_cast<const float4*>((isx ? x : w) + (size_t)row * DDIM);
    const float4* scl4 = reinterpret_cast<const float4*>(scales);

    float v[16];
    float m = 0.f;
    #pragma unroll
    for (int i = 0; i < 4; i++) {
        int g = i * 256 + tid;
        float4 xv = src4[g];
        float4 s  = scl4[g];
        float t0, t1, t2, t3;
        if (isx) { t0 = xv.x * s.x; t1 = xv.y * s.y; t2 = xv.z * s.z; t3 = xv.w * s.w; }
        else     { t0 = xv.x / s.x; t1 = xv.y / s.y; t2 = xv.z / s.z; t3 = xv.w / s.w; }
        v[i*4+0] = t0; v[i*4+1] = t1; v[i*4+2] = t2; v[i*4+3] = t3;
        m = fmaxf(m, fmaxf(fmaxf(fabsf(t0), fabsf(t1)), fmaxf(fabsf(t2), fabsf(t3))));
    }

    __shared__ float red[8];
    #pragma unroll
    for (int o = 16; o > 0; o >>= 1)
        m = fmaxf(m, __shfl_xor_sync(0xffffffffu, m, o));
    if ((tid & 31) == 0) red[tid >> 5] = m;
    __syncthreads();
    if (tid < 32) {
        float t = (tid < 8) ? red[tid] : 0.f;
        #pragma unroll
        for (int o = 4; o > 0; o >>= 1)
            t = fmaxf(t, __shfl_xor_sync(0xffffffffu, t, o));
        if (tid == 0) red[0] = fmaxf(t, 1e-8f);
    }
    __syncthreads();
    const float absmax = red[0];
    const float qs = 127.f / absmax;

    int* qrow = reinterpret_cast<int*>((isx ? g_qx : g_qw) + (size_t)row * DDIM);
    #pragma unroll
    for (int i = 0; i < 4; i++) {
        int g = i * 256 + tid;
        int packed = 0;
        #pragma unroll
        for (int j = 0; j < 4; j++) {
            float t = rintf(v[i*4+j] * qs);
            t = fminf(fmaxf(t, -127.f), 127.f);
            packed |= ((int)t & 0xff) << (8 * j);
        }
        qrow[g] = packed;
    }
    if (tid == 0) {
        if (isx) g_sa[row] = absmax * (1.f / 127.f);
        else     g_sw[row] = absmax * (1.f / 127.f);
    }
}

// ---------------- pipe-balanced hybrid GEMM ----------------
// CTA tile 128x256, 512 threads (16 warps), 1 CTA/SM (reg-bound).
//   wid 0-4  (LOW arbiter priority):  IMMA on n[176:256) + ALL cp.async loads
//       each warp: full 128m x 16n strip = 8 mtiles x 2 ntiles, 64 acc regs
//   wid 5-15 (HIGH priority): pure dp4a on n[0:176), thread tile 8m x 8n
// Warp ratio 5:11 balances measured per-warp pipe costs (tensor 16.45 : fma 8.73).
// Smem [ki][col], A stride 136 / B stride 264 (both = 8 mod 32); 16B-group XOR
// swizzle phys(g,ki) = (g ^ ((g>>3)&1)) ^ (ki&7) (bijective; R16-proven).
// K-chunk 16 ints, 3-stage ring, one __syncthreads per chunk.
#define NCHUNK (KINT / 16)       // 64
#define ASTR   136
#define BSTR   264
#define A_ST   (16 * ASTR)       // ints per A stage
#define B_ST   (16 * BSTR)       // ints per B stage
#define STG    (A_ST + B_ST)     // 6400 ints per stage
#define SMEM_BYTES (3 * STG * 4) // 76800

__global__ __launch_bounds__(512, 1) void gemm_bal_kernel(
    const float* __restrict__ bias, const float* __restrict__ scales,
    float* __restrict__ out)
{
    extern __shared__ int smem[];
    const int tid  = threadIdx.x;
    const int wid  = tid >> 5;
    const int lane = tid & 31;
    const int m0   = blockIdx.y * 128;
    const int n0   = blockIdx.x * 256;

    const int* qxi = reinterpret_cast<const int*>(g_qx);
    const int* qwi = reinterpret_cast<const int*>(g_qw);
    const uint32_t sBase = smem_u32(smem);

    if (wid < 5) {
        // ============ IMMA + loader warps (threads 0-159, LOW priority) ============
        const int t = tid;            // 0..159

        // loader: 6144 4B cells (A: 128 cols, B: 256 cols) x 16 ki
        auto load_stage = [&](int c) {
            const int s = c % 3;
            const uint32_t stBase = sBase + (uint32_t)(s * STG) * 4;
            for (int idx = t; idx < 6144; idx += 160) {
                int ki   = idx & 15;
                int cell = idx >> 4;              // 0..383
                int isB  = (cell >= 128);
                int col  = isB ? cell - 128 : cell;
                int gc   = col >> 2;
                int pcol = (((gc ^ ((gc >> 3) & 1)) ^ (ki & 7)) << 2) + (col & 3);
                if (isB) {
                    cp4(stBase + (uint32_t)(A_ST + ki * BSTR + pcol) * 4,
                        qwi + (size_t)(n0 + col) * KINT + c * 16 + ki);
                } else {
                    cp4(stBase + (uint32_t)(ki * ASTR + pcol) * 4,
                        qxi + (size_t)(m0 + col) * KINT + c * 16 + ki);
                }
            }
        };

        const int g   = lane >> 2;
        const int tig = lane & 3;
        const int gq  = g >> 2;       // 0..1
        const int go  = g & 3;
        const int klo = tig;
        const int khi = tig + 4;
        int acc[8][2][4];             // [mt][nt][c]
        #pragma unroll
        for (int i = 0; i < 8; i++)
            #pragma unroll
            for (int j = 0; j < 2; j++)
                #pragma unroll
                for (int k = 0; k < 4; k++) acc[i][j][k] = 0;

        load_stage(0); CP_COMMIT();
        load_stage(1); CP_COMMIT();
        for (int c = 0; c < NCHUNK; c++) {
            CP_WAIT(1);
            __syncthreads();
            if (c + 2 < NCHUNK) { load_stage(c + 2); CP_COMMIT(); }
            const int sO = (c % 3) * STG;
            #pragma unroll
            for (int ks = 0; ks < 2; ks++) {
                const int* rAlo = smem + sO + (ks * 8 + tig) * ASTR;
                const int* rAhi = smem + sO + (ks * 8 + tig + 4) * ASTR;
                const int* rBlo = smem + sO + A_ST + (ks * 8 + tig) * BSTR;
                const int* rBhi = smem + sO + A_ST + (ks * 8 + tig + 4) * BSTR;
                uint32_t b[2][2];
                #pragma unroll
                for (int nt = 0; nt < 2; nt++) {
                    int gb  = 44 + 4 * wid + 2 * nt + gq;    // B group (n >= 176)
                    int gbf = gb ^ ((gb >> 3) & 1);
                    b[nt][0] = (uint32_t)rBlo[((gbf ^ klo) << 2) + go];
                    b[nt][1] = (uint32_t)rBhi[((gbf ^ khi) << 2) + go];
                }
                #pragma unroll
                for (int mt = 0; mt < 8; mt++) {
                    int ga   = mt * 4 + gq;                  // group of col (16mt + g)
                    int ga2  = ga + 2;                       // group of col +8
                    int gaf  = ga  ^ ((ga  >> 3) & 1);
                    int ga2f = ga2 ^ ((ga2 >> 3) & 1);
                    uint32_t a[4];
                    a[0] = (uint32_t)rAlo[((gaf  ^ klo) << 2) + go];
                    a[1] = (uint32_t)rAlo[((ga2f ^ klo) << 2) + go];
                    a[2] = (uint32_t)rAhi[((gaf  ^ khi) << 2) + go];
                    a[3] = (uint32_t)rAhi[((ga2f ^ khi) << 2) + go];
                    imma16832(acc[mt][0], a, b[0]);
                    imma16832(acc[mt][1], a, b[1]);
                }
            }
        }

        // IMMA epilogue: n = n0+176+16*wid+8*nt+2*tig, m = m0+16*mt+(g | g+8)
        float fw[2][2], fb[2][2];
        #pragma unroll
        for (int nt = 0; nt < 2; nt++) {
            int n = n0 + 176 + 16 * wid + 8 * nt + 2 * tig;
            fw[nt][0] = g_sw[n];
            fw[nt][1] = g_sw[n + 1];
            fb[nt][0] = __ldg(&bias[n])     / __ldg(&scales[n]);
            fb[nt][1] = __ldg(&bias[n + 1]) / __ldg(&scales[n + 1]);
        }
        #pragma unroll
        for (int mt = 0; mt < 8; mt++) {
            int mA = m0 + 16 * mt + g;
            float saA = g_sa[mA];
            float saB = g_sa[mA + 8];
            #pragma unroll
            for (int nt = 0; nt < 2; nt++) {
                int n = n0 + 176 + 16 * wid + 8 * nt + 2 * tig;
                float2 o0, o1;
                o0.x = acc[mt][nt][0] * saA * fw[nt][0] + fb[nt][0];
                o0.y = acc[mt][nt][1] * saA * fw[nt][1] + fb[nt][1];
                o1.x = acc[mt][nt][2] * saB * fw[nt][0] + fb[nt][0];
                o1.y = acc[mt][nt][3] * saB * fw[nt][1] + fb[nt][1];
                *reinterpret_cast<float2*>(out + (size_t)mA       * N_ROWS + n) = o0;
                *reinterpret_cast<float2*>(out + (size_t)(mA + 8) * N_ROWS + n) = o1;
            }
        }
    } else {
        // ============ dp4a warps (threads 160-511, HIGH priority, no loads) ============
        const int t2 = tid - 160;     // 0..351
        const int ty = t2 / 22;       // 0..15: m rows ty*8+i
        const int tx = t2 % 22;       // 0..21: n cols tx*8+j
        const int tyg = 2 * ty;
        const int txg = 2 * tx;
        const int kA0 = tyg       ^ ((tyg >> 3) & 1);
        const int kA1 = (tyg + 1) ^ (((tyg + 1) >> 3) & 1);
        const int kB0 = txg       ^ ((txg >> 3) & 1);
        const int kB1 = (txg + 1) ^ (((txg + 1) >> 3) & 1);
        int acc[8][8];
        #pragma unroll
        for (int i = 0; i < 8; i++)
            #pragma unroll
            for (int j = 0; j < 8; j++) acc[i][j] = 0;

        for (int c = 0; c < NCHUNK; c++) {
            __syncthreads();          // stage c ready (loader warps waited before barrier)
            const int sO = (c % 3) * STG;
            #pragma unroll
            for (int ki = 0; ki < 16; ki++) {
                const int4* arow = reinterpret_cast<const int4*>(smem + sO + ki * ASTR);
                const int4* brow = reinterpret_cast<const int4*>(smem + sO + A_ST + ki * BSTR);
                const int k7 = ki & 7;
                int a[8], b[8];
                *reinterpret_cast<int4*>(&a[0]) = arow[kA0 ^ k7];
                *reinterpret_cast<int4*>(&a[4]) = arow[kA1 ^ k7];
                *reinterpret_cast<int4*>(&b[0]) = brow[kB0 ^ k7];
                *reinterpret_cast<int4*>(&b[4]) = brow[kB1 ^ k7];
                #pragma unroll
                for (int i = 0; i < 8; i++)
                    #pragma unroll
                    for (int j = 0; j < 8; j++)
                        acc[i][j] = __dp4a(a[i], b[j], acc[i][j]);
            }
        }

        // dp4a epilogue: m = m0+ty*8+i, n = n0+tx*8+j
        float fw[8], fb[8];
        #pragma unroll
        for (int j = 0; j < 8; j++) {
            int n = n0 + tx * 8 + j;
            fw[j] = g_sw[n];
            fb[j] = __ldg(&bias[n]) / __ldg(&scales[n]);
        }
        #pragma unroll
        for (int i = 0; i < 8; i++) {
            int m = m0 + ty * 8 + i;
            float fa = g_sa[m];
            float4 o0, o1;
            o0.x = acc[i][0]*fa*fw[0]+fb[0]; o0.y = acc[i][1]*fa*fw[1]+fb[1];
            o0.z = acc[i][2]*fa*fw[2]+fb[2]; o0.w = acc[i][3]*fa*fw[3]+fb[3];
            o1.x = acc[i][4]*fa*fw[4]+fb[4]; o1.y = acc[i][5]*fa*fw[5]+fb[5];
            o1.z = acc[i][6]*fa*fw[6]+fb[6]; o1.w = acc[i][7]*fa*fw[7]+fb[7];
            float4* orow = reinterpret_cast<float4*>(out + (size_t)m * N_ROWS + n0 + tx * 8);
            orow[0] = o0; orow[1] = o1;
        }
    }
}

// ---------------- launch ----------------
extern "C" void kernel_launch(void* const* d_in, const int* in_sizes, int n_in,
                              void* d_out, int out_size)
{
    const float* x      = (const float*)d_in[0];
    const float* weight = (const float*)d_in[1];
    const float* bias   = (const float*)d_in[2];
    const float* scales = (const float*)d_in[3];
    float* out = (float*)d_out;

    cudaFuncSetAttribute(gemm_bal_kernel,
                         cudaFuncAttributeMaxDynamicSharedMemorySize, SMEM_BYTES);

    quant_fused_kernel<<<M_ROWS + N_ROWS, 256>>>(x, weight, scales);

    dim3 grid(N_ROWS / 256, M_ROWS / 128);   // (16, 64)
    gemm_bal_kernel<<<grid, 512, SMEM_BYTES>>>(bias, scales, out);
}